// round 17
// baseline (speedup 1.0000x reference)
#include <cuda_runtime.h>
#include <cuda_fp16.h>
#include <cstdint>

// Problem constants (fixed by the dataset)
#define BATCH 2
#define CH    128
#define DW    64
#define DL    64
#define DH    64
#define SPAT  (DW*DL*DH)          // 262144
#define OUTW  7
#define OUTL  7
#define OUTH  7
#define NBINS (OUTW*OUTL*OUTH)    // 343

// Scratch: input transposed to (B, W, L, H, C) in fp16 so channels are
// contiguous. 2 * 262144 * 128 halves = 128 MB static device array.
__device__ __half g_vol[(size_t)BATCH * SPAT * CH];

struct alignas(8) H4 { __half2 a, b; };

// ---------------------------------------------------------------------------
// Kernel 1: transpose ONE batch: (C, S) fp32 -> (S, C) fp16, S = W*L*H.
// 32x32 tile, 256 threads. float4 global loads, 8-byte half4 global stores.
// (R10/R14 tiling — best measured.)
// ---------------------------------------------------------------------------
__global__ void __launch_bounds__(256)
transpose_half_kernel(const float* __restrict__ in, int b)
{
    __shared__ float tile[32][33];

    const int t  = threadIdx.x;
    const int s0 = blockIdx.x * 32;
    const int c0 = blockIdx.y * 32;

    // Phase 1: load float4 along spatial (contiguous). rows=channel.
    {
        const int c_local = t >> 3;          // 0..31
        const int s4      = t & 7;           // 0..7  (x4 spatial)
        const float4 v = *reinterpret_cast<const float4*>(
            in + ((size_t)(b * CH + c0 + c_local)) * SPAT + s0 + s4 * 4);
        tile[s4 * 4 + 0][c_local] = v.x;     // banks conflict-free
        tile[s4 * 4 + 1][c_local] = v.y;
        tile[s4 * 4 + 2][c_local] = v.z;
        tile[s4 * 4 + 3][c_local] = v.w;
    }
    __syncthreads();
    // Phase 2: write 4 consecutive channels as one 8-byte half4 store.
    {
        const int s_local = t >> 3;          // 0..31
        const int c4      = t & 7;           // 0..7  (x4 channels)
        H4 h;
        h.a = __floats2half2_rn(tile[s_local][c4 * 4 + 0], tile[s_local][c4 * 4 + 1]);
        h.b = __floats2half2_rn(tile[s_local][c4 * 4 + 2], tile[s_local][c4 * 4 + 3]);
        *reinterpret_cast<H4*>(
            g_vol + ((size_t)b * SPAT + s0 + s_local) * CH + c0 + c4 * 4) = h;
    }
}

// ---------------------------------------------------------------------------
// Kernel 2: ROI-align rotated 3D gather for ONE batch (blocks whose ROI is
// in another batch exit immediately).
// One warp per (roi, bin). Half-warps split the jz sample dimension;
// within a half-warp, lane owns 8 channels (one uint4 / 16B).
// Per-(jx,jy): 8 corner loads; per half2 slot an 8-product fp16 TREE
// (8 HMUL2 independent, depth-3 HADD2 tree), widened to fp32 per iteration.
// (R15 math — measured best.) Cross-half shfl reduce at end.
// ---------------------------------------------------------------------------
__device__ __forceinline__ __half2 h2(const unsigned int& u)
{
    return *reinterpret_cast<const __half2*>(&u);
}

__global__ void __launch_bounds__(256)
roi_gather_kernel(const float* __restrict__ rois,
                  const float* __restrict__ scale_p,
                  float* __restrict__ out,
                  int N, int target_b)
{
    const int n = blockIdx.y;
    const float* r = rois + (size_t)n * 8;
    const int b = (int)r[0];
    if (b != target_b) return;           // uniform across block: safe

    // 8 bins x 128 channels staging. float4 rows padded to 33 -> scalar reads
    // at pitch 132 floats are bank-conflict-free.
    __shared__ float4 s_out4[8][33];

    const int warp   = threadIdx.x >> 5;
    const int lane   = threadIdx.x & 31;
    const int zhalf  = lane >> 4;        // which jz sample this half-warp does
    const int laneIn = lane & 15;        // 8-channel group within half-warp
    const int bin    = blockIdx.x * 8 + warp;

    float a[8] = {0.f, 0.f, 0.f, 0.f, 0.f, 0.f, 0.f, 0.f};

    if (bin < NBINS) {
        const float scale = *scale_p;
        const float cx = r[1] * scale;
        const float cy = r[2] * scale;
        const float cz = r[3] * scale;
        const float sx = r[4] * scale;
        const float sy = r[5] * scale;
        const float sz = r[6] * scale;
        const float th = r[7];
        const float ct = cosf(th);
        const float st = sinf(th);

        // step = (size/nbins)/SR, matching reference arithmetic order
        const float stepx = (sx / 7.0f) * 0.5f;
        const float stepy = (sy / 7.0f) * 0.5f;
        const float stepz = (sz / 7.0f) * 0.5f;

        const int ow  = bin / 49;
        const int rem = bin % 49;
        const int ol  = rem / 7;
        const int oh  = rem % 7;

        // ---- z: loop-invariant for this lane (depends only on bin + zhalf)
        const int   iz = oh * 2 + zhalf;
        const float zs = (-sz * 0.5f + ((float)iz + 0.5f) * stepz) + cz;
        const float zval = ((zs > -1.0f) && (zs < (float)DH)) ? 1.0f : 0.0f;
        const float zc = fminf(fmaxf(zs, 0.f), (float)(DH - 1));
        const int   z0 = (int)floorf(zc);
        const float lz = zc - (float)z0;
        const float wz0 = (1.0f - lz) * zval;     // weight for z0 plane
        const float wz1 = lz * zval;              // weight for z1 plane
        const int   oz  = (z0 + 1 <= DH - 1) ? 256 : 0;

        // byte-addressed base for this lane's 8-channel slice (16B per voxel,
        // 256B per spatial step). All corner offsets fit in 32-bit ints.
        const char* __restrict__ vbase =
            reinterpret_cast<const char*>(g_vol) + (size_t)b * SPAT * 256 + laneIn * 16;

        #pragma unroll
        for (int jx = 0; jx < 2; ++jx) {
            const int ix = ow * 2 + jx;
            const float fx = -sx * 0.5f + ((float)ix + 0.5f) * stepx;
            #pragma unroll
            for (int jy = 0; jy < 2; ++jy) {
                const int iy = ol * 2 + jy;
                const float fy = -sy * 0.5f + ((float)iy + 0.5f) * stepy;
                const float xs = ct * fx - st * fy + cx;
                const float ys = st * fx + ct * fy + cy;

                const bool vxy = (xs > -1.0f) && (xs < (float)DW) &&
                                 (ys > -1.0f) && (ys < (float)DL);
                if (!vxy) continue;

                const float xc = fminf(fmaxf(xs, 0.f), (float)(DW - 1));
                const float yc = fminf(fmaxf(ys, 0.f), (float)(DL - 1));
                const int x0 = (int)floorf(xc);
                const int y0 = (int)floorf(yc);
                const float lx = xc - (float)x0, hx = 1.f - lx;
                const float ly = yc - (float)y0, hy = 1.f - ly;

                const int ox = (x0 + 1 <= DW - 1) ? (DL * DH * 256) : 0;
                const int oy = (y0 + 1 <= DL - 1) ? (DH * 256)      : 0;
                const int o000 = ((x0 * DL + y0) * DH + z0) * 256;

                // 8 corner loads (2x2 xy corners x 2 z planes), batched for MLP
                const uint4 v00a = *reinterpret_cast<const uint4*>(vbase + o000);
                const uint4 v00b = *reinterpret_cast<const uint4*>(vbase + o000 + oz);
                const uint4 v01a = *reinterpret_cast<const uint4*>(vbase + o000 + oy);
                const uint4 v01b = *reinterpret_cast<const uint4*>(vbase + o000 + oy + oz);
                const uint4 v10a = *reinterpret_cast<const uint4*>(vbase + o000 + ox);
                const uint4 v10b = *reinterpret_cast<const uint4*>(vbase + o000 + ox + oz);
                const uint4 v11a = *reinterpret_cast<const uint4*>(vbase + o000 + ox + oy);
                const uint4 v11b = *reinterpret_cast<const uint4*>(vbase + o000 + ox + oy + oz);

                const float wxy00 = hx * hy;
                const float wxy01 = hx * ly;
                const float wxy10 = lx * hy;
                const float wxy11 = lx * ly;

                // fp16 duplicated weights (one F2FP each)
                const __half2 w00a = __float2half2_rn(wxy00 * wz0);
                const __half2 w00b = __float2half2_rn(wxy00 * wz1);
                const __half2 w01a = __float2half2_rn(wxy01 * wz0);
                const __half2 w01b = __float2half2_rn(wxy01 * wz1);
                const __half2 w10a = __float2half2_rn(wxy10 * wz0);
                const __half2 w10b = __float2half2_rn(wxy10 * wz1);
                const __half2 w11a = __float2half2_rn(wxy11 * wz0);
                const __half2 w11b = __float2half2_rn(wxy11 * wz1);

                const unsigned int* q00a = reinterpret_cast<const unsigned int*>(&v00a);
                const unsigned int* q00b = reinterpret_cast<const unsigned int*>(&v00b);
                const unsigned int* q01a = reinterpret_cast<const unsigned int*>(&v01a);
                const unsigned int* q01b = reinterpret_cast<const unsigned int*>(&v01b);
                const unsigned int* q10a = reinterpret_cast<const unsigned int*>(&v10a);
                const unsigned int* q10b = reinterpret_cast<const unsigned int*>(&v10b);
                const unsigned int* q11a = reinterpret_cast<const unsigned int*>(&v11a);
                const unsigned int* q11b = reinterpret_cast<const unsigned int*>(&v11b);

                #pragma unroll
                for (int k = 0; k < 4; ++k) {
                    // 8 independent products
                    const __half2 p0 = __hmul2(h2(q00a[k]), w00a);
                    const __half2 p1 = __hmul2(h2(q00b[k]), w00b);
                    const __half2 p2 = __hmul2(h2(q01a[k]), w01a);
                    const __half2 p3 = __hmul2(h2(q01b[k]), w01b);
                    const __half2 p4 = __hmul2(h2(q10a[k]), w10a);
                    const __half2 p5 = __hmul2(h2(q10b[k]), w10b);
                    const __half2 p6 = __hmul2(h2(q11a[k]), w11a);
                    const __half2 p7 = __hmul2(h2(q11b[k]), w11b);
                    // depth-3 pairwise tree
                    const __half2 s0 = __hadd2(p0, p1);
                    const __half2 s1 = __hadd2(p2, p3);
                    const __half2 s2 = __hadd2(p4, p5);
                    const __half2 s3 = __hadd2(p6, p7);
                    const __half2 t0 = __hadd2(s0, s1);
                    const __half2 t1 = __hadd2(s2, s3);
                    const __half2 sum = __hadd2(t0, t1);
                    // widen once per slot per iteration
                    const float2 f = __half22float2(sum);
                    a[k * 2 + 0] += f.x;
                    a[k * 2 + 1] += f.y;
                }
            }
        }
    }

    // Combine the two jz halves: lane L and L+16 hold the same channels.
    #pragma unroll
    for (int k = 0; k < 8; ++k) {
        a[k] += __shfl_xor_sync(0xffffffffu, a[k], 16);
        a[k] *= 0.125f;
    }

    // Stage: lanes 0..15 write 8 channels = 2 float4 (STS.128).
    if (zhalf == 0) {
        s_out4[warp][laneIn * 2 + 0] = make_float4(a[0], a[1], a[2], a[3]);
        s_out4[warp][laneIn * 2 + 1] = make_float4(a[4], a[5], a[6], a[7]);
    }
    __syncthreads();

    // Write: bins contiguous in gmem (out[n][c][bin]). Each group of 8 lanes
    // writes 8 consecutive bins for one channel -> full 32B sectors.
    {
        const float* s_outf = reinterpret_cast<const float*>(s_out4);
        const int bin_local = threadIdx.x & 7;
        const int bin_g     = blockIdx.x * 8 + bin_local;
        if (bin_g < NBINS) {
            const int cbase = threadIdx.x >> 3;   // 0..31
            #pragma unroll
            for (int k = 0; k < 4; ++k) {
                const int c = cbase + 32 * k;
                out[((size_t)n * CH + c) * NBINS + bin_g] =
                    s_outf[bin_local * 132 + c];
            }
        }
    }
}

// ---------------------------------------------------------------------------
// Launch: batch-split pipeline.
//   main: T(b0) --e0--> T(b1) -> G(b1) --(wait e1)
//   s2:            \--> G(b0) --e1--/
// G(b0) overlaps T(b1): disjoint scratch regions, disjoint output rows.
// Streams/events are host-side objects (no device memory); created per call
// (correctness + capture calls only) and intentionally not destroyed.
// ---------------------------------------------------------------------------
extern "C" void kernel_launch(void* const* d_in, const int* in_sizes, int n_in,
                              void* d_out, int out_size)
{
    const float* input  = (const float*)d_in[0];
    const float* rois   = (const float*)d_in[1];
    const float* scale  = (const float*)d_in[2];
    float* out = (float*)d_out;
    const int N = in_sizes[1] / 8;

    cudaStream_t s2;
    cudaStreamCreateWithFlags(&s2, cudaStreamNonBlocking);
    cudaEvent_t e0, e1;
    cudaEventCreateWithFlags(&e0, cudaEventDisableTiming);
    cudaEventCreateWithFlags(&e1, cudaEventDisableTiming);

    const dim3 gridT(SPAT / 32, CH / 32);        // (8192, 4) per batch
    const dim3 gridG((NBINS + 7) / 8, N);        // (43, 128)

    // T(b0) on main
    transpose_half_kernel<<<gridT, 256>>>(input, 0);
    cudaEventRecord(e0, 0);

    // G(b0) on s2, after T(b0)
    cudaStreamWaitEvent(s2, e0, 0);
    roi_gather_kernel<<<gridG, 256, 0, s2>>>(rois, scale, out, N, 0);
    cudaEventRecord(e1, s2);

    // T(b1) then G(b1) on main (overlaps G(b0))
    transpose_half_kernel<<<gridT, 256>>>(input, 1);
    roi_gather_kernel<<<gridG, 256>>>(rois, scale, out, N, 1);

    // join s2 back into main
    cudaStreamWaitEvent(0, e1, 0);
}